// round 17
// baseline (speedup 1.0000x reference)
#include <cuda_runtime.h>
#include <cuda_fp16.h>
#include <math.h>
#include <stdint.h>

// Problem constants
#define BB   2
#define NN   4096
#define BNP  (BB*NN)        // 8192 rows
#define DIMV 256
#define KNNV 16
#define M2   (BNP*KNNV)     // 131072 rows

typedef __half h16;

// -------------------- scratch --------------------
__device__ float g_qa [BNP*DIMV];
__device__ float g_ka [BNP*DIMV];
__device__ h16   g_v  [BNP*DIMV];
__device__ h16   g_agg[BNP*DIMV];
__device__ int   g_idx[M2];
__device__ h16   g_h2 [(size_t)M2*DIMV];
__device__ h16   g_wt [7*DIMV*DIMV];       // transposed fp16 weights [n][k]
__device__ h16   g_xb [BNP*DIMV];
__device__ float g_bpa[DIMV];

#define WT_WV  0
#define WT_PW2 1
#define WT_AW2 2
#define WT_FW  3
#define WT_WQA 4
#define WT_WKA 5
#define WT_WPA 6

// epilogue flags
#define F_RELU    1
#define F_OH16    2
#define F_QK      4

#define LDSM4(r0, r1, r2, r3, addr)                                          \
    asm volatile("ldmatrix.sync.aligned.m8n8.x4.shared.b16 {%0,%1,%2,%3}, [%4];" \
                 : "=r"(r0), "=r"(r1), "=r"(r2), "=r"(r3) : "r"(addr))

#define MMA_F16(c0, c1, a0, a1, a2, a3, b0, b1)                              \
    asm volatile("mma.sync.aligned.m16n8k16.row.col.f16.f16.f16.f16 "        \
                 "{%0,%1}, {%2,%3,%4,%5}, {%6,%7}, {%0,%1};\n"               \
                 : "+r"(c0), "+r"(c1)                                        \
                 : "r"(a0), "r"(a1), "r"(a2), "r"(a3), "r"(b0), "r"(b1))

__device__ __forceinline__ void cp16h(h16* s, const h16* g) {
    uint32_t sa = (uint32_t)__cvta_generic_to_shared(s);
    asm volatile("cp.async.cg.shared.global [%0], [%1], 16;\n" :: "r"(sa), "l"(g));
}

// ==================== fp16 mma.sync GEMM (f16 acc), 512 threads ====
// CTA tile 128x128, BK=64 double-buffered. 16 warps (4x4), 32x32 per warp.
#define BKV   64
#define ASTR  72
#define TBUF  (128*ASTR)
#define GEMM_SMEM_BYTES (4*TBUF*2)  // 73728 B

__global__ __launch_bounds__(512, 2)
void gemm_f16_kernel(const h16* __restrict__ A,
                     const h16* __restrict__ Bt0, const h16* __restrict__ Bt1,
                     const h16* __restrict__ Bt2,
                     const float* __restrict__ bias0, const float* __restrict__ bias1,
                     const float* __restrict__ bias2,
                     const float* __restrict__ resid,
                     void* __restrict__ out0, void* __restrict__ out1,
                     void* __restrict__ out2,
                     int flags0, int flags1, int flags2)
{
    extern __shared__ h16 smem[];
    h16* As = smem;              // [2][128][ASTR]
    h16* Bs = smem + 2 * TBUF;   // [2][128][ASTR]

    const int tid  = threadIdx.x;
    const int lane = tid & 31;
    const int warp = tid >> 5;
    const int wm   = warp >> 2;
    const int wn   = warp & 3;
    const int bm   = blockIdx.y * 128;

    int sub, bn;
    if (Bt1) { sub = blockIdx.x >> 1; bn = (blockIdx.x & 1) * 128; }
    else     { sub = 0;               bn = blockIdx.x * 128; }
    const h16*   Bt    = (sub == 2) ? Bt2    : (sub == 1) ? Bt1    : Bt0;
    const float* bias  = (sub == 2) ? bias2  : (sub == 1) ? bias1  : bias0;
    void*        Cout  = (sub == 2) ? out2   : (sub == 1) ? out1   : out0;
    const int    flags = (sub == 2) ? flags2 : (sub == 1) ? flags1 : flags0;

    const int g  = lane >> 2;
    const int tg = lane & 3;

    uint32_t acc[2][4][2];
#pragma unroll
    for (int i = 0; i < 2; ++i)
#pragma unroll
        for (int j = 0; j < 4; ++j) { acc[i][j][0] = 0u; acc[i][j][1] = 0u; }

    auto load_tile = [&](int buf, int k0) {
#pragma unroll
        for (int u = 0; u < 2; ++u) {
            int idx = tid + u * 512;
            int row = idx >> 3;
            int c8  = idx & 7;
            cp16h(&As[buf * TBUF + row * ASTR + c8 * 8],
                  A + (size_t)(bm + row) * 256 + k0 + c8 * 8);
        }
#pragma unroll
        for (int u = 0; u < 2; ++u) {
            int idx = tid + u * 512;
            int row = idx >> 3;
            int c8  = idx & 7;
            cp16h(&Bs[buf * TBUF + row * ASTR + c8 * 8],
                  Bt + (size_t)(bn + row) * 256 + k0 + c8 * 8);
        }
        asm volatile("cp.async.commit_group;\n");
    };

    load_tile(0, 0);

    const int sel  = lane >> 3;
    const int rsub = lane & 7;
    const uint32_t sA = (uint32_t)__cvta_generic_to_shared(As);
    const uint32_t sB = (uint32_t)__cvta_generic_to_shared(Bs);
    const uint32_t aBase =
        sA + (uint32_t)(((wm * 32 + rsub + (sel & 1) * 8) * ASTR + (sel >> 1) * 8) * 2);
    const uint32_t bBase =
        sB + (uint32_t)(((wn * 32 + rsub + (sel & 1) * 8) * ASTR + (sel >> 1) * 8) * 2);

    for (int t = 0; t < 4; ++t) {
        const int buf = t & 1;
        if (t < 3) {
            load_tile(buf ^ 1, (t + 1) * BKV);
            asm volatile("cp.async.wait_group 1;\n" ::: "memory");
        } else {
            asm volatile("cp.async.wait_group 0;\n" ::: "memory");
        }
        __syncthreads();

        const uint32_t aT = aBase + (uint32_t)buf * (TBUF * 2);
        const uint32_t bT = bBase + (uint32_t)buf * (TBUF * 2);

#pragma unroll
        for (int ks = 0; ks < 4; ++ks) {
            const uint32_t koff = ks * 16 * 2;
            uint32_t af[2][4], bfr[4][2];
#pragma unroll
            for (int mt = 0; mt < 2; ++mt) {
                LDSM4(af[mt][0], af[mt][1], af[mt][2], af[mt][3],
                      aT + (uint32_t)(mt * 16 * ASTR * 2) + koff);
            }
#pragma unroll
            for (int p = 0; p < 2; ++p) {
                LDSM4(bfr[2 * p][0], bfr[2 * p + 1][0], bfr[2 * p][1], bfr[2 * p + 1][1],
                      bT + (uint32_t)(p * 16 * ASTR * 2) + koff);
            }
#pragma unroll
            for (int mt = 0; mt < 2; ++mt)
#pragma unroll
                for (int nt = 0; nt < 4; ++nt) {
                    MMA_F16(acc[mt][nt][0], acc[mt][nt][1],
                            af[mt][0], af[mt][1], af[mt][2], af[mt][3],
                            bfr[nt][0], bfr[nt][1]);
                }
        }
        __syncthreads();
    }

    const bool doRelu = flags & F_RELU;
    const bool oh16   = flags & F_OH16;
#pragma unroll
    for (int mt = 0; mt < 2; ++mt) {
#pragma unroll
        for (int nt = 0; nt < 4; ++nt) {
            int row0 = bm + wm * 32 + mt * 16 + g;
            int col0 = bn + wn * 32 + nt * 8 + 2 * tg;
            float2 lo = __half22float2(*(const __half2*)&acc[mt][nt][0]);
            float2 hi = __half22float2(*(const __half2*)&acc[mt][nt][1]);
#pragma unroll
            for (int h = 0; h < 2; ++h) {
                int row = row0 + h * 8;
                float c0 = h ? hi.x : lo.x;
                float c1 = h ? hi.y : lo.y;
                if (bias) { c0 += bias[col0]; c1 += bias[col0 + 1]; }
                if (doRelu) { c0 = fmaxf(c0, 0.f); c1 = fmaxf(c1, 0.f); }
                if (oh16) {
                    *(__half2*)((h16*)Cout + (size_t)row * 256 + col0) =
                        __floats2half2_rn(c0, c1);
                } else {
                    if (resid) {
                        c0 += resid[(size_t)row * 256 + col0];
                        c1 += resid[(size_t)row * 256 + col0 + 1];
                    }
                    *(float2*)((float*)Cout + (size_t)row * 256 + col0) =
                        make_float2(c0, c1);
                }
            }
        }
    }
}

// ==================== h2 GEMM with on-the-fly A = relu(rel@pw1+pb1) ====
// h2 = relu(h @ Wpa + bpa + qa[n] - ka[r]).  A generated per chunk from pos.
#define GEMMH_SMEM_BYTES (4*TBUF*2 + 4096)

__global__ __launch_bounds__(512, 2)
void gemm_h2_kernel(const float* __restrict__ pos,
                    const float* __restrict__ pw1, const float* __restrict__ pb1,
                    const h16* __restrict__ Bt, const float* __restrict__ bias,
                    const float* __restrict__ qa, const float* __restrict__ ka)
{
    extern __shared__ h16 smem[];
    h16* As = smem;              // [2][128][ASTR]
    h16* Bs = smem + 2 * TBUF;   // [2][128][ASTR]
    float* pw1s = (float*)(smem + 4 * TBUF);  // [3][256] + pb1 [256]

    const int tid  = threadIdx.x;
    const int lane = tid & 31;
    const int warp = tid >> 5;
    const int wm   = warp >> 2;
    const int wn   = warp & 3;
    const int bm   = blockIdx.y * 128;
    const int bn   = blockIdx.x * 128;

    const int g  = lane >> 2;
    const int tg = lane & 3;

    // stage pw1 (3x256) + pb1 (256) into smem
    for (int i = tid; i < 1024; i += 512)
        pw1s[i] = (i < 768) ? pw1[i] : pb1[i - 768];

    // per-thread rel (row = tid>>2)
    const int arow = tid >> 2;
    const int aq   = tid & 3;              // quarter: 16 channels each
    const int m    = bm + arow;
    const int nidx = m >> 4;
    const int ridx = g_idx[m];
    const float rx = pos[3 * nidx]     - pos[3 * ridx];
    const float ry = pos[3 * nidx + 1] - pos[3 * ridx + 1];
    const float rz = pos[3 * nidx + 2] - pos[3 * ridx + 2];

    uint32_t acc[2][4][2];
#pragma unroll
    for (int i = 0; i < 2; ++i)
#pragma unroll
        for (int j = 0; j < 4; ++j) { acc[i][j][0] = 0u; acc[i][j][1] = 0u; }

    auto cpB = [&](int buf, int k0) {
#pragma unroll
        for (int u = 0; u < 2; ++u) {
            int idx = tid + u * 512;
            int row = idx >> 3;
            int c8  = idx & 7;
            cp16h(&Bs[buf * TBUF + row * ASTR + c8 * 8],
                  Bt + (size_t)(bn + row) * 256 + k0 + c8 * 8);
        }
        asm volatile("cp.async.commit_group;\n");
    };
    auto genA = [&](int buf, int k0) {
        h16* dst = As + buf * TBUF + arow * ASTR + aq * 16;
#pragma unroll
        for (int j = 0; j < 16; j += 2) {
            int ch = k0 + aq * 16 + j;
            float v0 = pw1s[768 + ch] + rx * pw1s[ch] + ry * pw1s[256 + ch] + rz * pw1s[512 + ch];
            float v1 = pw1s[768 + ch + 1] + rx * pw1s[ch + 1] + ry * pw1s[256 + ch + 1] + rz * pw1s[512 + ch + 1];
            *(__half2*)(dst + j) = __floats2half2_rn(fmaxf(v0, 0.f), fmaxf(v1, 0.f));
        }
    };

    cpB(0, 0);
    __syncthreads();          // pw1s staged
    genA(0, 0);

    const int sel  = lane >> 3;
    const int rsub = lane & 7;
    const uint32_t sA = (uint32_t)__cvta_generic_to_shared(As);
    const uint32_t sB = (uint32_t)__cvta_generic_to_shared(Bs);
    const uint32_t aBase =
        sA + (uint32_t)(((wm * 32 + rsub + (sel & 1) * 8) * ASTR + (sel >> 1) * 8) * 2);
    const uint32_t bBase =
        sB + (uint32_t)(((wn * 32 + rsub + (sel & 1) * 8) * ASTR + (sel >> 1) * 8) * 2);

    for (int t = 0; t < 4; ++t) {
        const int buf = t & 1;
        if (t < 3) {
            cpB(buf ^ 1, (t + 1) * BKV);
            asm volatile("cp.async.wait_group 1;\n" ::: "memory");
        } else {
            asm volatile("cp.async.wait_group 0;\n" ::: "memory");
        }
        __syncthreads();                      // (1)
        if (t < 3) genA(buf ^ 1, (t + 1) * BKV);

        const uint32_t aT = aBase + (uint32_t)buf * (TBUF * 2);
        const uint32_t bT = bBase + (uint32_t)buf * (TBUF * 2);
#pragma unroll
        for (int ks = 0; ks < 4; ++ks) {
            const uint32_t koff = ks * 16 * 2;
            uint32_t af[2][4], bfr[4][2];
#pragma unroll
            for (int mt = 0; mt < 2; ++mt)
                LDSM4(af[mt][0], af[mt][1], af[mt][2], af[mt][3],
                      aT + (uint32_t)(mt * 16 * ASTR * 2) + koff);
#pragma unroll
            for (int p = 0; p < 2; ++p)
                LDSM4(bfr[2*p][0], bfr[2*p+1][0], bfr[2*p][1], bfr[2*p+1][1],
                      bT + (uint32_t)(p * 16 * ASTR * 2) + koff);
#pragma unroll
            for (int mt = 0; mt < 2; ++mt)
#pragma unroll
                for (int nt = 0; nt < 4; ++nt)
                    MMA_F16(acc[mt][nt][0], acc[mt][nt][1],
                            af[mt][0], af[mt][1], af[mt][2], af[mt][3],
                            bfr[nt][0], bfr[nt][1]);
        }
        __syncthreads();                      // (2)
    }

    // epilogue: + bias + qa[n] - ka[r], relu, fp16 out
#pragma unroll
    for (int mt = 0; mt < 2; ++mt) {
#pragma unroll
        for (int nt = 0; nt < 4; ++nt) {
            int row0 = bm + wm * 32 + mt * 16 + g;
            int col0 = bn + wn * 32 + nt * 8 + 2 * tg;
            float2 lo = __half22float2(*(const __half2*)&acc[mt][nt][0]);
            float2 hi = __half22float2(*(const __half2*)&acc[mt][nt][1]);
#pragma unroll
            for (int h = 0; h < 2; ++h) {
                int row = row0 + h * 8;
                float c0 = h ? hi.x : lo.x;
                float c1 = h ? hi.y : lo.y;
                c0 += bias[col0]; c1 += bias[col0 + 1];
                int n = row >> 4;
                int r = g_idx[row];
                float2 qv = *(const float2*)(qa + (size_t)n * 256 + col0);
                float2 kv = *(const float2*)(ka + (size_t)r * 256 + col0);
                c0 += qv.x - kv.x;
                c1 += qv.y - kv.y;
                c0 = fmaxf(c0, 0.f); c1 = fmaxf(c1, 0.f);
                *(__half2*)(g_h2 + (size_t)row * 256 + col0) =
                    __floats2half2_rn(c0, c1);
            }
        }
    }
}

// ==================== fused softagg: a2 = h2@aw2, pe = h@pw2, softmax+agg ====
// h generated on the fly from pos (slot1). BK=32 double-buffered.
#define SBK   32
#define SSTR  40
#define STILE (128*SSTR)
#define SOFT_SMEM_BYTES (8*STILE*2 + 4096)
#define PSTR  136

__global__ __launch_bounds__(512, 2)
void softagg_kernel(const float* __restrict__ pos,
                    const float* __restrict__ pw1, const float* __restrict__ pb1,
                    const float* __restrict__ ab2, const float* __restrict__ pb2)
{
    extern __shared__ h16 smem[];
    float* pw1s = (float*)(smem + 8 * STILE);   // [3][256] + pb1

    const int tid  = threadIdx.x;
    const int lane = tid & 31;
    const int warp = tid >> 5;
    const int wm   = warp >> 2;
    const int wn   = warp & 3;
    const int bm   = blockIdx.y * 128;
    const int bn   = blockIdx.x * 128;

    const h16* aw2t = g_wt + (size_t)WT_AW2 * 65536;
    const h16* pw2t = g_wt + (size_t)WT_PW2 * 65536;

    const int g  = lane >> 2;
    const int tg = lane & 3;

    // stage pw1/pb1
    for (int i = tid; i < 1024; i += 512)
        pw1s[i] = (i < 768) ? pw1[i] : pb1[i - 768];

    // per-thread rel (row = tid>>2)
    const int lrow = tid >> 2;
    const int lc4  = tid & 3;
    const int m    = bm + lrow;
    const int nidx = m >> 4;
    const int ridx = g_idx[m];
    const float rx = pos[3 * nidx]     - pos[3 * ridx];
    const float ry = pos[3 * nidx + 1] - pos[3 * ridx + 1];
    const float rz = pos[3 * nidx + 2] - pos[3 * ridx + 2];

    uint32_t acc_a2[2][4][2], acc_pe[2][4][2];
#pragma unroll
    for (int i = 0; i < 2; ++i)
#pragma unroll
        for (int j = 0; j < 4; ++j) {
            acc_a2[i][j][0] = acc_a2[i][j][1] = 0u;
            acc_pe[i][j][0] = acc_pe[i][j][1] = 0u;
        }

    auto cp_part = [&](int buf, int k0) {
        h16* base = smem + (size_t)buf * 4 * STILE + lrow * SSTR + lc4 * 8;
        const size_t goffA = (size_t)m * 256 + k0 + lc4 * 8;
        const size_t goffB = (size_t)(bn + lrow) * 256 + k0 + lc4 * 8;
        cp16h(base,             g_h2 + goffA);
        cp16h(base + 2 * STILE, aw2t + goffB);
        cp16h(base + 3 * STILE, pw2t + goffB);
        asm volatile("cp.async.commit_group;\n");
    };
    auto gen_h = [&](int buf, int k0) {
        h16* dst = smem + (size_t)buf * 4 * STILE + STILE + lrow * SSTR + lc4 * 8;
#pragma unroll
        for (int j = 0; j < 8; j += 2) {
            int ch = k0 + lc4 * 8 + j;
            float v0 = pw1s[768 + ch] + rx * pw1s[ch] + ry * pw1s[256 + ch] + rz * pw1s[512 + ch];
            float v1 = pw1s[768 + ch + 1] + rx * pw1s[ch + 1] + ry * pw1s[256 + ch + 1] + rz * pw1s[512 + ch + 1];
            *(__half2*)(dst + j) = __floats2half2_rn(fmaxf(v0, 0.f), fmaxf(v1, 0.f));
        }
    };

    cp_part(0, 0);
    __syncthreads();          // pw1s staged
    gen_h(0, 0);

    const int sel  = lane >> 3;
    const int rsub = lane & 7;
    const uint32_t sBase = (uint32_t)__cvta_generic_to_shared(smem);
    const uint32_t aOff =
        (uint32_t)(((wm * 32 + rsub + (sel & 1) * 8) * SSTR + (sel >> 1) * 8) * 2);
    const uint32_t bOff =
        (uint32_t)(((wn * 32 + rsub + (sel & 1) * 8) * SSTR + (sel >> 1) * 8) * 2);

    for (int t = 0; t < 8; ++t) {
        const int buf = t & 1;
        if (t < 7) {
            cp_part(buf ^ 1, (t + 1) * SBK);
            asm volatile("cp.async.wait_group 1;\n" ::: "memory");
        } else {
            asm volatile("cp.async.wait_group 0;\n" ::: "memory");
        }
        __syncthreads();                    // (1)
        if (t < 7) gen_h(buf ^ 1, (t + 1) * SBK);

        const uint32_t tb = sBase + (uint32_t)buf * (4 * STILE * 2);

#pragma unroll
        for (int ks = 0; ks < 2; ++ks) {
            const uint32_t koff = ks * 16 * 2;
            {   // a2 += h2 @ aw2
                uint32_t af[2][4], bfr[4][2];
#pragma unroll
                for (int mt = 0; mt < 2; ++mt)
                    LDSM4(af[mt][0], af[mt][1], af[mt][2], af[mt][3],
                          tb + aOff + (uint32_t)(mt * 16 * SSTR * 2) + koff);
#pragma unroll
                for (int p = 0; p < 2; ++p)
                    LDSM4(bfr[2*p][0], bfr[2*p+1][0], bfr[2*p][1], bfr[2*p+1][1],
                          tb + (uint32_t)(2 * STILE * 2) + bOff
                             + (uint32_t)(p * 16 * SSTR * 2) + koff);
#pragma unroll
                for (int mt = 0; mt < 2; ++mt)
#pragma unroll
                    for (int nt = 0; nt < 4; ++nt)
                        MMA_F16(acc_a2[mt][nt][0], acc_a2[mt][nt][1],
                                af[mt][0], af[mt][1], af[mt][2], af[mt][3],
                                bfr[nt][0], bfr[nt][1]);
            }
            {   // pe += h @ pw2
                uint32_t af[2][4], bfr[4][2];
#pragma unroll
                for (int mt = 0; mt < 2; ++mt)
                    LDSM4(af[mt][0], af[mt][1], af[mt][2], af[mt][3],
                          tb + (uint32_t)(STILE * 2) + aOff
                             + (uint32_t)(mt * 16 * SSTR * 2) + koff);
#pragma unroll
                for (int p = 0; p < 2; ++p)
                    LDSM4(bfr[2*p][0], bfr[2*p+1][0], bfr[2*p][1], bfr[2*p+1][1],
                          tb + (uint32_t)(3 * STILE * 2) + bOff
                             + (uint32_t)(p * 16 * SSTR * 2) + koff);
#pragma unroll
                for (int mt = 0; mt < 2; ++mt)
#pragma unroll
                    for (int nt = 0; nt < 4; ++nt)
                        MMA_F16(acc_pe[mt][nt][0], acc_pe[mt][nt][1],
                                af[mt][0], af[mt][1], af[mt][2], af[mt][3],
                                bfr[nt][0], bfr[nt][1]);
            }
        }
        __syncthreads();                    // (2)
    }

    // stage a2 (scaled+bias) and pe (bias) as fp16
    h16* sa2 = smem;                  // [128][PSTR]
    h16* spe = smem + 128 * PSTR;
    const float inv_scale = 1.0f / 16.0f;
#pragma unroll
    for (int mt = 0; mt < 2; ++mt)
#pragma unroll
        for (int nt = 0; nt < 4; ++nt) {
            int rl = wm * 32 + mt * 16 + g;
            int cl = wn * 32 + nt * 8 + 2 * tg;
            float b0 = ab2[bn + cl], b1 = ab2[bn + cl + 1];
            float p0 = pb2[bn + cl], p1 = pb2[bn + cl + 1];
            float2 lo = __half22float2(*(const __half2*)&acc_a2[mt][nt][0]);
            float2 hi = __half22float2(*(const __half2*)&acc_a2[mt][nt][1]);
            *(__half2*)(sa2 + rl * PSTR + cl) =
                __floats2half2_rn((lo.x + b0) * inv_scale, (lo.y + b1) * inv_scale);
            *(__half2*)(sa2 + (rl + 8) * PSTR + cl) =
                __floats2half2_rn((hi.x + b0) * inv_scale, (hi.y + b1) * inv_scale);
            float2 plo = __half22float2(*(const __half2*)&acc_pe[mt][nt][0]);
            float2 phi = __half22float2(*(const __half2*)&acc_pe[mt][nt][1]);
            *(__half2*)(spe + rl * PSTR + cl) =
                __floats2half2_rn(plo.x + p0, plo.y + p1);
            *(__half2*)(spe + (rl + 8) * PSTR + cl) =
                __floats2half2_rn(phi.x + p0, phi.y + p1);
        }
    __syncthreads();

    // per-(query, channel) softmax over K + aggregate
#pragma unroll
    for (int i = 0; i < 2; ++i) {
        const int p  = tid + i * 512;
        const int q  = p >> 7;
        const int c  = p & 127;
        const int m0 = bm + q * 16;
        float vals[KNNV];
        float mx = -3.4e38f;
#pragma unroll
        for (int k = 0; k < KNNV; ++k) {
            vals[k] = __half2float(sa2[(q * 16 + k) * PSTR + c]);
            mx = fmaxf(mx, vals[k]);
        }
        float s = 0.f, accv = 0.f;
#pragma unroll
        for (int k = 0; k < KNNV; ++k) {
            float e = __expf(vals[k] - mx);
            int r = g_idx[m0 + k];
            float pv = __half2float(spe[(q * 16 + k) * PSTR + c])
                     + __half2float(g_v[(size_t)r * 256 + bn + c]);
            s += e;
            accv = fmaf(e, pv, accv);
        }
        const int qg = m0 >> 4;
        g_agg[(size_t)qg * 256 + bn + c] = __float2half_rn(accv / s);
    }
}

// -------------------- prep --------------------
struct WSrcs { const float* p[4]; };   // wv, pw2, aw2, fw

__global__ __launch_bounds__(256)
void conv_weights_kernel(WSrcs ws)
{
    const int sel = blockIdx.x >> 8;
    const int n   = blockIdx.x & 255;
    const int k   = threadIdx.x;
    g_wt[(size_t)sel * 65536 + n * 256 + k] =
        __float2half_rn(ws.p[sel][k * 256 + n]);
}

__global__ __launch_bounds__(256)
void fold_kernel(const float* __restrict__ wq, const float* __restrict__ wk,
                 const float* __restrict__ pw2, const float* __restrict__ aw1,
                 const float* __restrict__ pb2, const float* __restrict__ ab1)
{
    const int b = blockIdx.x;
    const int j = threadIdx.x;
    if (b < 768) {
        const int sel = b >> 8;
        const int i   = b & 255;
        const float* src = (sel == 0) ? wq : (sel == 1) ? wk : pw2;
        float s = 0.f;
        for (int d = 0; d < 256; ++d)
            s = fmaf(src[i * 256 + d], aw1[d * 256 + j], s);
        g_wt[(size_t)(WT_WQA + sel) * 65536 + j * 256 + i] = __float2half_rn(s);
    } else {
        float s = ab1[j];
        for (int d = 0; d < 256; ++d)
            s = fmaf(pb2[d], aw1[d * 256 + j], s);
        g_bpa[j] = s;
    }
}

__global__ __launch_bounds__(256)
void conv_x_kernel(const float* __restrict__ x)
{
    const int i4 = blockIdx.x * 256 + threadIdx.x;
    if (i4 < BNP * DIMV / 4) {
        float4 v = *(const float4*)(x + (size_t)i4 * 4);
        __half2* o = (__half2*)(g_xb + (size_t)i4 * 4);
        o[0] = __floats2half2_rn(v.x, v.y);
        o[1] = __floats2half2_rn(v.z, v.w);
    }
}

// -------------------- KNN --------------------
__device__ __forceinline__ bool dless(float d1, int i1, float d2, int i2) {
    return (d1 < d2) || (d1 == d2 && i1 < i2);
}

#define KNN_SMEM_BYTES (4 * NN * 4)

__global__ __launch_bounds__(256)
void knn_kernel(const float* __restrict__ pos)
{
    extern __shared__ float sm[];
    float* px = sm;
    float* py = sm + NN;
    float* pz = sm + 2 * NN;
    float* sj = sm + 3 * NN;

    const int b = blockIdx.x >> 9;
    const float* pb = pos + (size_t)b * NN * 3;
    for (int j = threadIdx.x; j < NN; j += 256) {
        float x = pb[3 * j], y = pb[3 * j + 1], z = pb[3 * j + 2];
        px[j] = x; py[j] = y; pz[j] = z;
        sj[j] = x * x + y * y + z * z;
    }
    __syncthreads();

    const int warp = threadIdx.x >> 5, lane = threadIdx.x & 31;
    const int q  = blockIdx.x * 8 + warp;
    const int ql = q & (NN - 1);
    const float qx = px[ql], qy = py[ql], qz = pz[ql];
    const float qsq = sj[ql];

    const unsigned FULL = 0xffffffffu;
    float ld  = 3.4e38f; int li   = 0x7fffffff;
    float tau = 3.4e38f; int taui = 0x7fffffff;

#define KNN_INSERT(cd, cj)                                             \
    {                                                                  \
        bool keep = dless(ld, li, (cd), (cj));                         \
        unsigned bal = __ballot_sync(FULL, keep) & 0xffffu;            \
        int p = __popc(bal);                                           \
        float pd = __shfl_up_sync(FULL, ld, 1);                        \
        int   pi = __shfl_up_sync(FULL, li, 1);                        \
        if (lane == p) { ld = (cd); li = (cj); }                       \
        else if (lane > p && lane < 16) { ld = pd; li = pi; }          \
        tau  = __shfl_sync(FULL, ld, 15);                              \
        taui = __shfl_sync(FULL, li, 15);                              \
    }

#define KNN_HANDLE(dd, jj)                                             \
    {                                                                  \
        unsigned any = __ballot_sync(FULL, dless(dd, jj, tau, taui));  \
        while (any) {                                                  \
            int src = __ffs(any) - 1; any &= any - 1;                  \
            float cd = __shfl_sync(FULL, dd, src);                     \
            int   cj = __shfl_sync(FULL, jj, src);                     \
            if (dless(cd, cj, tau, taui)) KNN_INSERT(cd, cj);          \
        }                                                              \
    }

    for (int base = 0; base < NN; base += 128) {
        const int j0 = base + lane;
        const int j1 = j0 + 32;
        const int j2 = j0 + 64;
        const int j3 = j0 + 96;
        float d0 = qsq + sj[j0] - 2.f * (qx * px[j0] + qy * py[j0] + qz * pz[j0]);
        float d1 = qsq + sj[j1] - 2.f * (qx * px[j1] + qy * py[j1] + qz * pz[j1]);
        float d2 = qsq + sj[j2] - 2.f * (qx * px[j2] + qy * py[j2] + qz * pz[j2]);
        float d3 = qsq + sj[j3] - 2.f * (qx * px[j3] + qy * py[j3] + qz * pz[j3]);
        KNN_HANDLE(d0, j0)
        KNN_HANDLE(d1, j1)
        KNN_HANDLE(d2, j2)
        KNN_HANDLE(d3, j3)
    }

    if (lane < KNNV) g_idx[q * KNNV + lane] = b * NN + li;
#undef KNN_INSERT
#undef KNN_HANDLE
}

// -------------------- launch --------------------
extern "C" void kernel_launch(void* const* d_in, const int* in_sizes, int n_in,
                              void* d_out, int out_size)
{
    const float* x   = (const float*)d_in[0];
    const float* pos = (const float*)d_in[1];
    const float* wq  = (const float*)d_in[2];
    const float* wk  = (const float*)d_in[3];
    const float* wv  = (const float*)d_in[4];
    const float* pw1 = (const float*)d_in[5];
    const float* pb1 = (const float*)d_in[6];
    const float* pw2 = (const float*)d_in[7];
    const float* pb2 = (const float*)d_in[8];
    const float* aw1 = (const float*)d_in[9];
    const float* ab1 = (const float*)d_in[10];
    const float* aw2 = (const float*)d_in[11];
    const float* ab2 = (const float*)d_in[12];
    const float* fw  = (const float*)d_in[13];
    const float* fb  = (const float*)d_in[14];
    (void)in_sizes; (void)n_in; (void)out_size;

    float *qa, *ka, *bpa;
    h16 *v, *agg, *h2, *wt, *xb;
    cudaGetSymbolAddress((void**)&qa,  g_qa);
    cudaGetSymbolAddress((void**)&ka,  g_ka);
    cudaGetSymbolAddress((void**)&v,   g_v);
    cudaGetSymbolAddress((void**)&agg, g_agg);
    cudaGetSymbolAddress((void**)&h2,  g_h2);
    cudaGetSymbolAddress((void**)&wt,  g_wt);
    cudaGetSymbolAddress((void**)&xb,  g_xb);
    cudaGetSymbolAddress((void**)&bpa, g_bpa);

    cudaFuncSetAttribute(gemm_f16_kernel,
                         cudaFuncAttributeMaxDynamicSharedMemorySize, GEMM_SMEM_BYTES);
    cudaFuncSetAttribute(gemm_h2_kernel,
                         cudaFuncAttributeMaxDynamicSharedMemorySize, GEMMH_SMEM_BYTES);
    cudaFuncSetAttribute(softagg_kernel,
                         cudaFuncAttributeMaxDynamicSharedMemorySize, SOFT_SMEM_BYTES);
    cudaFuncSetAttribute(knn_kernel,
                         cudaFuncAttributeMaxDynamicSharedMemorySize, KNN_SMEM_BYTES);

    const h16* wvt  = wt + (size_t)WT_WV  * 65536;
    const h16* fwt  = wt + (size_t)WT_FW  * 65536;
    const h16* wqat = wt + (size_t)WT_WQA * 65536;
    const h16* wkat = wt + (size_t)WT_WKA * 65536;
    const h16* wpat = wt + (size_t)WT_WPA * 65536;

    dim3 blk(256);
    dim3 gblk(512);

    // prep
    WSrcs ws; ws.p[0] = wv; ws.p[1] = pw2; ws.p[2] = aw2; ws.p[3] = fw;
    conv_weights_kernel<<<1024, blk>>>(ws);
    fold_kernel<<<769, blk>>>(wq, wk, pw2, aw1, pb2, ab1);
    conv_x_kernel<<<BNP * DIMV / 4 / 256, blk>>>(x);

    // qa, ka, v (triple: fp32, fp32, fp16 outs)
    gemm_f16_kernel<<<dim3(6, BNP / 128), gblk, GEMM_SMEM_BYTES>>>(
        xb, wqat, wkat, wvt, nullptr, nullptr, nullptr,
        nullptr,
        qa, ka, v, 0, 0, F_OH16);

    // knn
    knn_kernel<<<BNP / 8, blk, KNN_SMEM_BYTES>>>(pos);

    // h2 = relu(h@Wpa + bpa + qa[n] - ka[r]),  h generated on the fly
    gemm_h2_kernel<<<dim3(2, M2 / 128), gblk, GEMMH_SMEM_BYTES>>>(
        pos, pw1, pb1, wpat, bpa, qa, ka);

    // fused: a2 = h2@aw2+ab2, pe = h@pw2+pb2 (h on the fly), softmax+agg
    softagg_kernel<<<dim3(2, M2 / 128), gblk, SOFT_SMEM_BYTES>>>(
        pos, pw1, pb1, ab2, pb2);

    // out = agg@fw + fb + x
    gemm_f16_kernel<<<dim3(2, BNP / 128), gblk, GEMM_SMEM_BYTES>>>(
        agg, fwt, nullptr, nullptr, fb, nullptr, nullptr,
        x,
        (float*)d_out, nullptr, nullptr, 0, 0, 0);
}